// round 14
// baseline (speedup 1.0000x reference)
#include <cuda_runtime.h>

// Soft quantizer forward == hard nearest-level quantization (straight-through).
// levels[k] = -1 + k*(2/24), k = 0..24.
//
// HBM-streaming kernel at the DRAM roofline (~7.2 TB/s effective). Persistent
// grid (152 SMs x 5 CTAs = 760 blocks), 256 threads/block, 128B per thread
// per tile. This round: stores widened to 256-bit (st.global.cs.v8.b32,
// sm_100+) to halve store issue traffic; loads remain the proven 128-bit
// __ldcg, re-tiled into adjacent float4 pairs (float8 units, 32B lane
// stride — every 128B line fully consumed by the companion load pair).

#define Z_MIN   (-1.0f)
#define STEP    (2.0f / 24.0f)
#define INVSTEP (12.0f)
#define LMAX    (24.0f)

__device__ __forceinline__ float quant1(float x) {
    float k = rintf((x - Z_MIN) * INVSTEP);
    k = fminf(fmaxf(k, 0.0f), LMAX);
    return fmaf(k, STEP, Z_MIN);
}

__device__ __forceinline__ float4 quant4(float4 a) {
    float4 r;
    r.x = quant1(a.x); r.y = quant1(a.y); r.z = quant1(a.z); r.w = quant1(a.w);
    return r;
}

// 256-bit streaming store (evict-first). sm_100+ only.
__device__ __forceinline__ void st8_stream(float* p, float4 a, float4 b) {
    asm volatile("st.global.cs.v8.b32 [%0], {%1,%2,%3,%4,%5,%6,%7,%8};"
                 :: "l"(p),
                    "f"(a.x), "f"(a.y), "f"(a.z), "f"(a.w),
                    "f"(b.x), "f"(b.y), "f"(b.z), "f"(b.w)
                 : "memory");
}

#define TILE8 4                  // float8 units per thread per tile (128B total)
#define NTHR 256                 // threads per block
#define TILE_F8 (NTHR * TILE8)   // float8s per tile = 1024 (= 32KB * 256thr... 256KB/tile)

__global__ void __launch_bounds__(NTHR) quant_kernel_pers8(const float* __restrict__ in,
                                                           float* __restrict__ out,
                                                           int n8, int ntiles) {
    const float4* in4 = (const float4*)in;

    for (int t = blockIdx.x; t < ntiles; t += gridDim.x) {
        int base = t * TILE_F8 + threadIdx.x;   // float8 index

        if (base + (TILE8 - 1) * NTHR < n8) {
            // fast path: full tile in range
            float4 lo[TILE8], hi[TILE8];
            #pragma unroll
            for (int j = 0; j < TILE8; j++) {
                int i8 = base + j * NTHR;
                lo[j] = __ldcg(&in4[2 * i8]);       // 8 front-batched LDG.128
                hi[j] = __ldcg(&in4[2 * i8 + 1]);
            }
            #pragma unroll
            for (int j = 0; j < TILE8; j++) {
                lo[j] = quant4(lo[j]);
                hi[j] = quant4(hi[j]);
            }
            #pragma unroll
            for (int j = 0; j < TILE8; j++) {
                int i8 = base + j * NTHR;
                st8_stream(out + (size_t)i8 * 8, lo[j], hi[j]);   // 4 STG.256
            }
        } else {
            #pragma unroll
            for (int j = 0; j < TILE8; j++) {
                int i8 = base + j * NTHR;
                if (i8 < n8) {
                    float4 a = quant4(__ldcg(&in4[2 * i8]));
                    float4 b = quant4(__ldcg(&in4[2 * i8 + 1]));
                    st8_stream(out + (size_t)i8 * 8, a, b);
                }
            }
        }
    }
}

__global__ void __launch_bounds__(256) quant_kernel_tail(const float* __restrict__ in,
                                                         float* __restrict__ out,
                                                         int start, int n) {
    int i = start + blockIdx.x * blockDim.x + threadIdx.x;
    if (i < n) out[i] = quant1(in[i]);
}

extern "C" void kernel_launch(void* const* d_in, const int* in_sizes, int n_in,
                              void* d_out, int out_size) {
    const float* x = (const float*)d_in[0];
    float* out = (float*)d_out;
    int n = in_sizes[0];

    int n8 = n / 8;                  // full float8 chunks
    int tail_start = n8 * 8;

    if (n8 > 0) {
        int ntiles = (n8 + TILE_F8 - 1) / TILE_F8;
        int blocks = 152 * 5;        // one full resident wave (GB300: 152 SMs)
        if (blocks > ntiles) blocks = ntiles;
        quant_kernel_pers8<<<blocks, NTHR>>>(x, out, n8, ntiles);
    }
    if (tail_start < n) {
        int rem = n - tail_start;
        int threads = 256;
        int blocks = (rem + threads - 1) / threads;
        quant_kernel_tail<<<blocks, threads>>>(x, out, tail_start, n);
    }
}

// round 15
// speedup vs baseline: 1.2457x; 1.2457x over previous
#include <cuda_runtime.h>

// Soft quantizer forward == hard nearest-level quantization (straight-through).
// levels[k] = -1 + k*(2/24), k = 0..24.
//
// FINAL (champion, R10/R12, reverified): HBM-streaming kernel at the DRAM
// roofline — 134MB/replay at ~18.8us = ~7.16 TB/s effective, ~90% of the
// 8 TB/s HBM3e spec. Persistent grid-stride kernel, one resident wave of
// 152 SMs x 5 CTAs = 760 blocks, 256 threads/block, TILE=8 float4 per
// thread per tile (128B): 8 front-batched __ldcg LDG.128 (L2-cached,
// L1-bypass) + 8 __stcs STG.128 (evict-first) per tile.
//
// Full sweep record (dur_us): v4 23.2 | tile4 21.0 | ld256+evict_last 25.1 |
// tile8 19.0 | tile16 31.5 | tile8/128thr 21.0 | pers740 18.9 | pers1024 19.4 |
// pers760 18.75* | pers912 19.2 | pers760 rerun 18.91* | st256 23.0.
// 256-bit global ops regress steady-state on sm_103a graph replays; 128-bit
// is categorically correct here.

#define Z_MIN   (-1.0f)
#define STEP    (2.0f / 24.0f)
#define INVSTEP (12.0f)
#define LMAX    (24.0f)

__device__ __forceinline__ float quant1(float x) {
    float k = rintf((x - Z_MIN) * INVSTEP);
    k = fminf(fmaxf(k, 0.0f), LMAX);
    return fmaf(k, STEP, Z_MIN);
}

__device__ __forceinline__ float4 quant4(float4 a) {
    float4 r;
    r.x = quant1(a.x); r.y = quant1(a.y); r.z = quant1(a.z); r.w = quant1(a.w);
    return r;
}

#define TILE 8                  // float4s per thread per tile (128B)
#define NTHR 256                // threads per block
#define TILE_F4 (NTHR * TILE)   // float4s per tile = 2048

__global__ void __launch_bounds__(NTHR) quant_kernel_pers(const float4* __restrict__ in,
                                                          float4* __restrict__ out,
                                                          int n4, int ntiles) {
    for (int t = blockIdx.x; t < ntiles; t += gridDim.x) {
        int base = t * TILE_F4 + threadIdx.x;

        if (base + (TILE - 1) * NTHR < n4) {
            // fast path: full tile in range (all tiles except possibly the last)
            float4 v[TILE];
            #pragma unroll
            for (int j = 0; j < TILE; j++) v[j] = __ldcg(&in[base + j * NTHR]);
            #pragma unroll
            for (int j = 0; j < TILE; j++) v[j] = quant4(v[j]);
            #pragma unroll
            for (int j = 0; j < TILE; j++) __stcs(&out[base + j * NTHR], v[j]);
        } else {
            #pragma unroll
            for (int j = 0; j < TILE; j++) {
                int i = base + j * NTHR;
                if (i < n4) __stcs(&out[i], quant4(__ldcg(&in[i])));
            }
        }
    }
}

__global__ void __launch_bounds__(256) quant_kernel_tail(const float* __restrict__ in,
                                                         float* __restrict__ out,
                                                         int start, int n) {
    int i = start + blockIdx.x * blockDim.x + threadIdx.x;
    if (i < n) out[i] = quant1(in[i]);
}

extern "C" void kernel_launch(void* const* d_in, const int* in_sizes, int n_in,
                              void* d_out, int out_size) {
    const float* x = (const float*)d_in[0];
    float* out = (float*)d_out;
    int n = in_sizes[0];

    int n4 = n / 4;
    int tail_start = n4 * 4;

    if (n4 > 0) {
        int ntiles = (n4 + TILE_F4 - 1) / TILE_F4;   // 2048 for this shape
        int blocks = 152 * 5;                        // one full resident wave (GB300: 152 SMs)
        if (blocks > ntiles) blocks = ntiles;
        quant_kernel_pers<<<blocks, NTHR>>>((const float4*)x, (float4*)out, n4, ntiles);
    }
    if (tail_start < n) {
        int rem = n - tail_start;
        int threads = 256;
        int blocks = (rem + threads - 1) / threads;
        quant_kernel_tail<<<blocks, threads>>>(x, out, tail_start, n);
    }
}